// round 3
// baseline (speedup 1.0000x reference)
#include <cuda_runtime.h>
#include <cuda_bf16.h>

// ---------------------------------------------------------------------------
// NGNN GCNConv: h = GCNConv(x) ; relu ; relu(h@Wfc^T+bfc) ; @Wfc2^T+bfc2
// N=100000 nodes, C=128 channels everywhere, E=3.2M edges.
// ---------------------------------------------------------------------------

#define MAX_N 100000
#define C 128

// Scratch (device globals: allocation inside kernel_launch is forbidden)
__device__ __align__(256) float g_deg [MAX_N];
__device__ __align__(256) float g_dinv[MAX_N];
__device__ __align__(256) float g_h   [(size_t)MAX_N * C];
__device__ __align__(256) float g_agg [(size_t)MAX_N * C];
__device__ __align__(256) float g_h2  [(size_t)MAX_N * C];
__device__ int g_is64;

// ---------------------------------------------------------------------------
// Detect whether edge_index is int64 or int32 (JAX may silently downcast).
// If int64 (values < 2^31, nonnegative), every odd 32-bit word is zero.
// ---------------------------------------------------------------------------
__global__ void k_detect64(const unsigned int* __restrict__ ei32) {
    __shared__ unsigned s_any;
    if (threadIdx.x == 0) s_any = 0u;
    __syncthreads();
    unsigned any = 0u;
    for (int i = threadIdx.x; i < 4096; i += blockDim.x)
        any |= ei32[2 * i + 1];
    if (any) atomicOr(&s_any, 1u);
    __syncthreads();
    if (threadIdx.x == 0) g_is64 = (s_any == 0u) ? 1 : 0;
}

// deg[i] = 1.0 (self-loop weight); dinv placeholder
__global__ void k_init_deg(int n) {
    int i = blockIdx.x * blockDim.x + threadIdx.x;
    if (i < n) g_deg[i] = 1.0f;
}

__global__ void k_deg_accum(const void* __restrict__ ei,
                            const float* __restrict__ ew, long long E) {
    long long e = (long long)blockIdx.x * blockDim.x + threadIdx.x;
    if (e >= E) return;
    long long d;
    if (g_is64) d = ((const long long*)ei)[E + e];
    else        d = ((const int*)ei)[E + e];
    atomicAdd(&g_deg[d], ew[e]);
}

__global__ void k_dinv(int n) {
    int i = blockIdx.x * blockDim.x + threadIdx.x;
    if (i < n) {
        float dg = g_deg[i];
        g_dinv[i] = (dg > 0.0f) ? rsqrtf(dg) : 0.0f;
    }
}

// agg init = self-loop contribution: agg[i] = h[i] * dinv[i]^2  (float4 wide)
__global__ void k_self_init(int n) {
    long long idx = (long long)blockIdx.x * blockDim.x + threadIdx.x; // float4 idx
    long long total = (long long)n * (C / 4);
    if (idx >= total) return;
    int row = (int)(idx >> 5); // C/4 = 32 float4 per row
    float di = g_dinv[row];
    float s = di * di;
    float4 v = *(const float4*)&g_h[idx * 4];
    v.x *= s; v.y *= s; v.z *= s; v.w *= s;
    *(float4*)&g_agg[idx * 4] = v;
}

// ---------------------------------------------------------------------------
// Edge aggregation: one warp per edge; lane handles 4 channels (float4).
// agg[dst] += h[src] * (dinv[src]*ew*dinv[dst])   via red.global.add.v4.f32
// ---------------------------------------------------------------------------
__global__ void k_edge_agg(const void* __restrict__ ei,
                           const float* __restrict__ ew, long long E) {
    long long e = (long long)blockIdx.x * (blockDim.x / 32) + (threadIdx.x >> 5);
    if (e >= E) return;
    int lane = threadIdx.x & 31;
    long long s, d;
    if (g_is64) {
        s = ((const long long*)ei)[e];
        d = ((const long long*)ei)[E + e];
    } else {
        s = ((const int*)ei)[e];
        d = ((const int*)ei)[E + e];
    }
    float norm = g_dinv[s] * ew[e] * g_dinv[d];
    const float4 hv = *(const float4*)&g_h[s * C + lane * 4];
    float a = hv.x * norm, b = hv.y * norm, c = hv.z * norm, w = hv.w * norm;
    float* dst = &g_agg[d * C + lane * 4];
    asm volatile("red.global.add.v4.f32 [%0], {%1, %2, %3, %4};"
                 :: "l"(dst), "f"(a), "f"(b), "f"(c), "f"(w) : "memory");
}

// ---------------------------------------------------------------------------
// Fused 128-wide GEMM:  Cout[i,j] = post( sum_k pre(A[i,k]) * W[j,k] )
//   PRE : pre(a) = relu(a + preb[k])    (bias + relu applied to input)
//   POSTB: += postb[j]
//   POSTR: relu
// Block = 256 threads, tile = 32 rows x 128 cols. W transposed into smem
// with row stride 132 (pad 4) -> conflict-free float4 reads; 4x4 register
// blocking -> 16 FFMA per LDS.128.
// ---------------------------------------------------------------------------
#define WS_STRIDE 132
#define GEMM_SMEM_BYTES ((128 * WS_STRIDE + 32 * 128) * 4)

template <int PRE, int POSTB, int POSTR>
__global__ __launch_bounds__(256) void k_gemm128(
    const float* __restrict__ A, const float* __restrict__ W,
    const float* __restrict__ preb, const float* __restrict__ postb,
    float* __restrict__ Cout, int n) {
    extern __shared__ float smem[];
    float* Ws = smem;                   // [128][132]  Ws[k][j] = W[j][k]
    float* As = smem + 128 * WS_STRIDE; // [32][128]

    int tid = threadIdx.x;
    for (int idx = tid; idx < 128 * 128; idx += 256) {
        int j = idx >> 7, k = idx & 127;
        Ws[k * WS_STRIDE + j] = W[idx];
    }
    int row0 = blockIdx.x * 32;
    for (int idx = tid; idx < 32 * 128; idx += 256) {
        int r = idx >> 7, k = idx & 127;
        int row = row0 + r;
        float v = 0.0f;
        if (row < n) {
            v = A[(long long)row * C + k];
            if (PRE) v = fmaxf(v + preb[k], 0.0f);
        }
        As[idx] = v;
    }
    __syncthreads();

    int warp = tid >> 5, lane = tid & 31;
    int rbase = warp * 4;
    int cbase = lane * 4;
    float acc[4][4] = {};

#pragma unroll 8
    for (int k = 0; k < 128; k++) {
        float4 w = *(const float4*)&Ws[k * WS_STRIDE + cbase];
#pragma unroll
        for (int r = 0; r < 4; r++) {
            float a = As[(rbase + r) * 128 + k];
            acc[r][0] += a * w.x;
            acc[r][1] += a * w.y;
            acc[r][2] += a * w.z;
            acc[r][3] += a * w.w;
        }
    }

#pragma unroll
    for (int r = 0; r < 4; r++) {
        int row = row0 + rbase + r;
        if (row < n) {
            float4 o = make_float4(acc[r][0], acc[r][1], acc[r][2], acc[r][3]);
            if (POSTB) {
                o.x += postb[cbase + 0];
                o.y += postb[cbase + 1];
                o.z += postb[cbase + 2];
                o.w += postb[cbase + 3];
            }
            if (POSTR) {
                o.x = fmaxf(o.x, 0.0f);
                o.y = fmaxf(o.y, 0.0f);
                o.z = fmaxf(o.z, 0.0f);
                o.w = fmaxf(o.w, 0.0f);
            }
            *(float4*)&Cout[(long long)row * C + cbase] = o;
        }
    }
}

// ---------------------------------------------------------------------------
extern "C" void kernel_launch(void* const* d_in, const int* in_sizes, int n_in,
                              void* d_out, int out_size) {
    const float* x  = (const float*)d_in[0];
    const void*  ei = d_in[1];
    const float* ew = (const float*)d_in[2];
    const float* Wc = (const float*)d_in[3];
    const float* bc = (const float*)d_in[4];
    const float* Wf = (const float*)d_in[5];
    const float* bf = (const float*)d_in[6];
    const float* W2 = (const float*)d_in[7];
    const float* b2 = (const float*)d_in[8];
    float* out = (float*)d_out;

    int n = in_sizes[0] / C;
    long long E = in_sizes[2];

    cudaFuncSetAttribute(k_gemm128<0, 0, 0>,
                         cudaFuncAttributeMaxDynamicSharedMemorySize, GEMM_SMEM_BYTES);
    cudaFuncSetAttribute(k_gemm128<1, 1, 1>,
                         cudaFuncAttributeMaxDynamicSharedMemorySize, GEMM_SMEM_BYTES);
    cudaFuncSetAttribute(k_gemm128<0, 1, 0>,
                         cudaFuncAttributeMaxDynamicSharedMemorySize, GEMM_SMEM_BYTES);

    float* g_h_p;   cudaGetSymbolAddress((void**)&g_h_p,   g_h);
    float* g_agg_p; cudaGetSymbolAddress((void**)&g_agg_p, g_agg);
    float* g_h2_p;  cudaGetSymbolAddress((void**)&g_h2_p,  g_h2);

    // 1. dtype detection for edge_index
    k_detect64<<<1, 256>>>((const unsigned int*)ei);

    // 2. degree (self-loops contribute 1.0 each)
    k_init_deg<<<(n + 255) / 256, 256>>>(n);
    k_deg_accum<<<(unsigned)((E + 255) / 256), 256>>>(ei, ew, E);
    k_dinv<<<(n + 255) / 256, 256>>>(n);

    // 3. h = x @ W_conv^T   (bias-free)
    int gemm_blocks = (n + 31) / 32;
    k_gemm128<0, 0, 0><<<gemm_blocks, 256, GEMM_SMEM_BYTES>>>(
        x, Wc, nullptr, nullptr, g_h_p, n);

    // 4. agg = self-loop term, then scatter-add edges
    long long tot4 = (long long)n * (C / 4);
    k_self_init<<<(unsigned)((tot4 + 255) / 256), 256>>>(n);
    k_edge_agg<<<(unsigned)((E + 7) / 8), 256>>>(ei, ew, E);

    // 5. h2 = relu( relu(agg + b_conv) @ W_fc^T + b_fc )
    k_gemm128<1, 1, 1><<<gemm_blocks, 256, GEMM_SMEM_BYTES>>>(
        g_agg_p, Wf, bc, bf, g_h2_p, n);

    // 6. out = h2 @ W_fc2^T + b_fc2
    k_gemm128<0, 1, 0><<<gemm_blocks, 256, GEMM_SMEM_BYTES>>>(
        g_h2_p, W2, nullptr, b2, out, n);
}

// round 4
// speedup vs baseline: 1.5379x; 1.5379x over previous
#include <cuda_runtime.h>
#include <cuda_bf16.h>

// ---------------------------------------------------------------------------
// NGNN GCNConv: h = GCNConv(x) ; relu ; relu(h@Wfc^T+bfc) ; @Wfc2^T+bfc2
// N=100000 nodes, C=128 channels, E=3.2M edges.
// Round 3: counting-sort (atomic-free) aggregation + f32x2 packed-FMA GEMMs.
// ---------------------------------------------------------------------------

#define MAX_N 100000
#define MAX_E 3200000
#define C 128

// Scratch (device globals: allocation inside kernel_launch is forbidden)
__device__ __align__(256) float g_deg   [MAX_N];
__device__ __align__(256) float g_dinv  [MAX_N];
__device__ __align__(256) int   g_cnt   [MAX_N];
__device__ __align__(256) int   g_start [MAX_N];
__device__ __align__(256) int   g_cursor[MAX_N];
__device__ __align__(256) int   g_bsum  [512];
__device__ __align__(256) int   g_boff  [512];
__device__ __align__(256) int2  g_ebuf  [MAX_E];            // {src, norm}
__device__ __align__(256) float g_h     [(size_t)MAX_N * C];
__device__ __align__(256) float g_agg   [(size_t)MAX_N * C];
__device__ __align__(256) float g_h2    [(size_t)MAX_N * C];
__device__ __align__(256) float g_WT    [3][128 * 128];     // transposed weights
__device__ int g_is64;

// ---------------------------------------------------------------------------
// edge_index dtype detection (JAX may silently emit int32 instead of int64):
// for int64 indices < 2^31, every odd 32-bit word is zero.
// ---------------------------------------------------------------------------
__global__ void k_detect64(const unsigned int* __restrict__ ei32) {
    __shared__ unsigned s_any;
    if (threadIdx.x == 0) s_any = 0u;
    __syncthreads();
    unsigned any = 0u;
    for (int i = threadIdx.x; i < 4096; i += blockDim.x)
        any |= ei32[2 * i + 1];
    if (any) atomicOr(&s_any, 1u);
    __syncthreads();
    if (threadIdx.x == 0) g_is64 = (s_any == 0u) ? 1 : 0;
}

__device__ __forceinline__ long long eidx(const void* ei, long long i) {
    return g_is64 ? ((const long long*)ei)[i]
                  : (long long)((const int*)ei)[i];
}

// deg = 1.0 (self-loop), cnt = 0
__global__ void k_init(int n) {
    int i = blockIdx.x * blockDim.x + threadIdx.x;
    if (i < n) { g_deg[i] = 1.0f; g_cnt[i] = 0; }
}

// transpose all three weight matrices once: WT[w][k*128+j] = W_w[j*128+k]
__global__ void k_transpose3(const float* __restrict__ W0,
                             const float* __restrict__ W1,
                             const float* __restrict__ W2) {
    int which = blockIdx.x >> 6;                       // 64 blocks per matrix
    int idx = ((blockIdx.x & 63) << 8) + threadIdx.x;  // 0..16383
    const float* W = (which == 0) ? W0 : (which == 1) ? W1 : W2;
    int k = idx >> 7, j = idx & 127;
    g_WT[which][idx] = W[j * 128 + k];
}

// per-edge: degree (weighted) + bucket counts
__global__ void k_deg_cnt(const void* __restrict__ ei,
                          const float* __restrict__ ew, long long E) {
    long long e = (long long)blockIdx.x * blockDim.x + threadIdx.x;
    if (e >= E) return;
    long long d = eidx(ei, E + e);
    atomicAdd(&g_deg[d], ew[e]);
    atomicAdd(&g_cnt[d], 1);
}

__global__ void k_dinv(int n) {
    int i = blockIdx.x * blockDim.x + threadIdx.x;
    if (i < n) {
        float dg = g_deg[i];
        g_dinv[i] = (dg > 0.0f) ? rsqrtf(dg) : 0.0f;
    }
}

// ---- exclusive prefix sum over g_cnt (3 stages) ----
__global__ void k_scanA(int n) {   // per-block reduction -> g_bsum
    __shared__ int sm[256];
    int t = threadIdx.x;
    int i = blockIdx.x * 256 + t;
    sm[t] = (i < n) ? g_cnt[i] : 0;
    __syncthreads();
    for (int s = 128; s > 0; s >>= 1) {
        if (t < s) sm[t] += sm[t + s];
        __syncthreads();
    }
    if (t == 0) g_bsum[blockIdx.x] = sm[0];
}

__global__ void k_scanB(int nb) {  // scan of block sums -> g_boff (exclusive)
    __shared__ int sm[512];
    int t = threadIdx.x;
    int v = (t < nb) ? g_bsum[t] : 0;
    sm[t] = v;
    __syncthreads();
    for (int off = 1; off < 512; off <<= 1) {
        int x = (t >= off) ? sm[t - off] : 0;
        __syncthreads();
        sm[t] += x;
        __syncthreads();
    }
    if (t < nb) g_boff[t] = sm[t] - v;  // exclusive
}

__global__ void k_scanC(int n) {   // final offsets -> g_start, g_cursor
    __shared__ int sm[256];
    int t = threadIdx.x;
    int i = blockIdx.x * 256 + t;
    int v = (i < n) ? g_cnt[i] : 0;
    sm[t] = v;
    __syncthreads();
    for (int off = 1; off < 256; off <<= 1) {
        int x = (t >= off) ? sm[t - off] : 0;
        __syncthreads();
        sm[t] += x;
        __syncthreads();
    }
    if (i < n) {
        int start = g_boff[blockIdx.x] + sm[t] - v;  // exclusive
        g_start[i] = start;
        g_cursor[i] = start;
    }
}

// scatter {src, norm} into dst-ordered buckets
__global__ void k_scatter(const void* __restrict__ ei,
                          const float* __restrict__ ew, long long E) {
    long long e = (long long)blockIdx.x * blockDim.x + threadIdx.x;
    if (e >= E) return;
    long long s = eidx(ei, e);
    long long d = eidx(ei, E + e);
    float nm = g_dinv[s] * ew[e] * g_dinv[d];
    int pos = atomicAdd(&g_cursor[d], 1);
    g_ebuf[pos] = make_int2((int)s, __float_as_int(nm));
}

// ---------------------------------------------------------------------------
// Gather: one warp per dst node, lane = 4 channels (float4). Atomic-free.
// agg[d] = dinv[d]^2 * h[d] + sum_bucket norm * h[src]
// ---------------------------------------------------------------------------
__global__ void k_gather(int n) {
    int w = (int)(((long long)blockIdx.x * blockDim.x + threadIdx.x) >> 5);
    if (w >= n) return;
    int lane = threadIdx.x & 31;
    int beg = g_start[w];
    int num = g_cnt[w];
    float di = g_dinv[w];
    float self = di * di;

    const float4* hrow = (const float4*)&g_h[(long long)w * C];
    float4 hv = hrow[lane];
    float4 acc = make_float4(hv.x * self, hv.y * self, hv.z * self, hv.w * self);

    int i = 0;
    for (; i + 4 <= num; i += 4) {
        int2 e0 = g_ebuf[beg + i];
        int2 e1 = g_ebuf[beg + i + 1];
        int2 e2 = g_ebuf[beg + i + 2];
        int2 e3 = g_ebuf[beg + i + 3];
        float4 h0 = *(const float4*)&g_h[(long long)e0.x * C + lane * 4];
        float4 h1 = *(const float4*)&g_h[(long long)e1.x * C + lane * 4];
        float4 h2 = *(const float4*)&g_h[(long long)e2.x * C + lane * 4];
        float4 h3 = *(const float4*)&g_h[(long long)e3.x * C + lane * 4];
        float n0 = __int_as_float(e0.y), n1 = __int_as_float(e1.y);
        float n2 = __int_as_float(e2.y), n3 = __int_as_float(e3.y);
        acc.x += n0 * h0.x; acc.y += n0 * h0.y; acc.z += n0 * h0.z; acc.w += n0 * h0.w;
        acc.x += n1 * h1.x; acc.y += n1 * h1.y; acc.z += n1 * h1.z; acc.w += n1 * h1.w;
        acc.x += n2 * h2.x; acc.y += n2 * h2.y; acc.z += n2 * h2.z; acc.w += n2 * h2.w;
        acc.x += n3 * h3.x; acc.y += n3 * h3.y; acc.z += n3 * h3.z; acc.w += n3 * h3.w;
    }
    for (; i < num; i++) {
        int2 e0 = g_ebuf[beg + i];
        float4 h0 = *(const float4*)&g_h[(long long)e0.x * C + lane * 4];
        float n0 = __int_as_float(e0.y);
        acc.x += n0 * h0.x; acc.y += n0 * h0.y; acc.z += n0 * h0.z; acc.w += n0 * h0.w;
    }
    *(float4*)&g_agg[(long long)w * C + lane * 4] = acc;
}

// ---------------------------------------------------------------------------
// 128-wide GEMM with f32x2 packed FMA (2x fp32 throughput, exact fp32).
// Cout[i,j] = post( sum_k pre(A[i,k]) * W[j,k] ),  WT pre-transposed.
// Block 256 thr, tile 64 rows x 128 cols, 4 rows x 8 cols per thread.
// ---------------------------------------------------------------------------
#define WS_STRIDE 132
#define TILE_R 64
#define GEMM_SMEM_BYTES ((128 * WS_STRIDE + TILE_R * 128) * 4)

template <int PRE, int POSTB, int POSTR>
__global__ __launch_bounds__(256, 2) void k_gemm128(
    const float* __restrict__ A, const float* __restrict__ WT,
    const float* __restrict__ preb, const float* __restrict__ postb,
    float* __restrict__ Cout, int n) {
    extern __shared__ float smem[];
    float* Ws = smem;                       // [128][132]  Ws[k][j]
    float* As = smem + 128 * WS_STRIDE;     // [64][128]

    int tid = threadIdx.x;
    for (int idx = tid; idx < 128 * 128; idx += 256)
        Ws[(idx >> 7) * WS_STRIDE + (idx & 127)] = WT[idx];  // conflict-free

    int row0 = blockIdx.x * TILE_R;
    for (int idx = tid; idx < TILE_R * 128; idx += 256) {
        int r = idx >> 7, k = idx & 127;
        int row = row0 + r;
        float v = 0.0f;
        if (row < n) {
            v = A[(long long)row * C + k];
            if (PRE) v = fmaxf(v + preb[k], 0.0f);
        }
        As[idx] = v;
    }
    __syncthreads();

    int cg = tid & 15, rg = tid >> 4;
    int cbase = cg * 8, rbase = rg * 4;

    unsigned long long acc[4][4];
#pragma unroll
    for (int r = 0; r < 4; r++)
#pragma unroll
        for (int p = 0; p < 4; p++) acc[r][p] = 0ull;

#pragma unroll 4
    for (int k = 0; k < 128; k++) {
        ulonglong2 wa = *(const ulonglong2*)&Ws[k * WS_STRIDE + cbase];
        ulonglong2 wb = *(const ulonglong2*)&Ws[k * WS_STRIDE + cbase + 4];
#pragma unroll
        for (int r = 0; r < 4; r++) {
            float a = As[(rbase + r) * 128 + k];
            unsigned long long aa;
            asm("mov.b64 %0, {%1, %1};" : "=l"(aa) : "f"(a));
            asm("fma.rn.f32x2 %0, %1, %2, %0;" : "+l"(acc[r][0]) : "l"(aa), "l"(wa.x));
            asm("fma.rn.f32x2 %0, %1, %2, %0;" : "+l"(acc[r][1]) : "l"(aa), "l"(wa.y));
            asm("fma.rn.f32x2 %0, %1, %2, %0;" : "+l"(acc[r][2]) : "l"(aa), "l"(wb.x));
            asm("fma.rn.f32x2 %0, %1, %2, %0;" : "+l"(acc[r][3]) : "l"(aa), "l"(wb.y));
        }
    }

#pragma unroll
    for (int r = 0; r < 4; r++) {
        int row = row0 + rbase + r;
        if (row >= n) continue;
        float o[8];
#pragma unroll
        for (int p = 0; p < 4; p++)
            asm("mov.b64 {%0, %1}, %2;"
                : "=f"(o[2 * p]), "=f"(o[2 * p + 1]) : "l"(acc[r][p]));
        if (POSTB) {
#pragma unroll
            for (int j = 0; j < 8; j++) o[j] += postb[cbase + j];
        }
        if (POSTR) {
#pragma unroll
            for (int j = 0; j < 8; j++) o[j] = fmaxf(o[j], 0.0f);
        }
        *(float4*)&Cout[(long long)row * C + cbase] =
            make_float4(o[0], o[1], o[2], o[3]);
        *(float4*)&Cout[(long long)row * C + cbase + 4] =
            make_float4(o[4], o[5], o[6], o[7]);
    }
}

// ---------------------------------------------------------------------------
extern "C" void kernel_launch(void* const* d_in, const int* in_sizes, int n_in,
                              void* d_out, int out_size) {
    const float* x  = (const float*)d_in[0];
    const void*  ei = d_in[1];
    const float* ew = (const float*)d_in[2];
    const float* Wc = (const float*)d_in[3];
    const float* bc = (const float*)d_in[4];
    const float* Wf = (const float*)d_in[5];
    const float* bf = (const float*)d_in[6];
    const float* W2 = (const float*)d_in[7];
    const float* b2 = (const float*)d_in[8];
    float* out = (float*)d_out;

    int n = in_sizes[0] / C;
    long long E = in_sizes[2];
    int nb = (n + 255) / 256;
    int gemm_blocks = (n + TILE_R - 1) / TILE_R;
    unsigned eblocks = (unsigned)((E + 255) / 256);

    cudaFuncSetAttribute(k_gemm128<0, 0, 0>,
                         cudaFuncAttributeMaxDynamicSharedMemorySize, GEMM_SMEM_BYTES);
    cudaFuncSetAttribute(k_gemm128<1, 1, 1>,
                         cudaFuncAttributeMaxDynamicSharedMemorySize, GEMM_SMEM_BYTES);
    cudaFuncSetAttribute(k_gemm128<0, 1, 0>,
                         cudaFuncAttributeMaxDynamicSharedMemorySize, GEMM_SMEM_BYTES);

    float* g_h_p;   cudaGetSymbolAddress((void**)&g_h_p,   g_h);
    float* g_agg_p; cudaGetSymbolAddress((void**)&g_agg_p, g_agg);
    float* g_h2_p;  cudaGetSymbolAddress((void**)&g_h2_p,  g_h2);
    float* g_WT_p;  cudaGetSymbolAddress((void**)&g_WT_p,  g_WT);
    const float* WTc = g_WT_p;
    const float* WTf = g_WT_p + 16384;
    const float* WT2 = g_WT_p + 32768;

    // 1. dtype detection
    k_detect64<<<1, 256>>>((const unsigned int*)ei);
    // 2. deg=1, cnt=0
    k_init<<<nb, 256>>>(n);
    // 3. weight transposes (once)
    k_transpose3<<<192, 256>>>(Wc, Wf, W2);
    // 4. weighted degree + bucket counts
    k_deg_cnt<<<eblocks, 256>>>(ei, ew, E);
    // 5. dinv
    k_dinv<<<nb, 256>>>(n);
    // 6. h = x @ Wc^T   (profiled launch under ncu -s 5 -c 1)
    k_gemm128<0, 0, 0><<<gemm_blocks, 256, GEMM_SMEM_BYTES>>>(
        x, WTc, nullptr, nullptr, g_h_p, n);
    // 7-9. exclusive prefix sum of counts
    k_scanA<<<nb, 256>>>(n);
    k_scanB<<<1, 512>>>(nb);
    k_scanC<<<nb, 256>>>(n);
    // 10. scatter edges into dst buckets
    k_scatter<<<eblocks, 256>>>(ei, ew, E);
    // 11. atomic-free gather (includes self-loop term)
    k_gather<<<(n * 32 + 255) / 256, 256>>>(n);
    // 12. h2 = relu( relu(agg + bc) @ Wf^T + bf )
    k_gemm128<1, 1, 1><<<gemm_blocks, 256, GEMM_SMEM_BYTES>>>(
        g_agg_p, WTf, bc, bf, g_h2_p, n);
    // 13. out = h2 @ W2^T + b2
    k_gemm128<0, 1, 0><<<gemm_blocks, 256, GEMM_SMEM_BYTES>>>(
        g_h2_p, WT2, nullptr, b2, out, n);
}